// round 1
// baseline (speedup 1.0000x reference)
#include <cuda_runtime.h>
#include <math.h>

#define NF   48
#define NM   51
#define KK   49
#define IMG  256
#define NB   16
#define TABN 2049
#define AS   72   // a-tile smem row stride
#define XS   80   // x-tile smem row stride

// ---- device scratch (static globals: allowed) ----
__device__ float  g_w[NF * 52];          // normalized weights, padded rows
__device__ float2 g_tab[NF][TABN];       // (value, delta) per filter
__device__ float  g_r[NB * IMG * IMG];   // residual r
__device__ float  g_partial[NB * 16];    // per-tile sum(r^2)
__device__ float  g_scale[NB];           // per-batch prox scale

// ---------------- K1: normalize conv weights ----------------
__global__ void prep_kernel(const float* __restrict__ cw, const float* __restrict__ sf) {
    int f = threadIdx.x;
    if (f >= NF) return;
    float mean = 0.f;
    #pragma unroll
    for (int i = 0; i < KK; i++) mean += cw[f * KK + i];
    mean *= (1.f / 49.f);
    float ss = 0.f;
    #pragma unroll
    for (int i = 0; i < KK; i++) { float d = cw[f * KK + i] - mean; ss += d * d; }
    float s = sf[f] / (sqrtf(ss) + 1e-12f);
    #pragma unroll
    for (int i = 0; i < KK; i++) g_w[f * 52 + i] = (cw[f * KK + i] - mean) * s;
    #pragma unroll
    for (int i = KK; i < 52; i++) g_w[f * 52 + i] = 0.f;
}

// ---------------- K2: build per-filter RBF lookup table ----------------
// T_f(z) = sum_m rbfw[f,m] * exp(-0.01*(z-c_m)^2), z on [-16,16], 2049 pts
__global__ void table_kernel(const float* __restrict__ rbw, const float* __restrict__ rbc) {
    __shared__ float wsh[NM], csh[NM];
    __shared__ float tsh[TABN];
    int f = blockIdx.x;
    int tid = threadIdx.x;
    if (tid < NM) { wsh[tid] = rbw[f * NM + tid]; csh[tid] = rbc[tid]; }
    __syncthreads();
    for (int k = tid; k < TABN; k += blockDim.x) {
        float z = -16.f + (float)k * (1.f / 64.f);
        float acc = 0.f;
        #pragma unroll
        for (int m = 0; m < NM; m++) {
            float d = z - csh[m];
            acc += wsh[m] * __expf(-0.01f * d * d);
        }
        tsh[k] = acc;
    }
    __syncthreads();
    for (int k = tid; k < TABN; k += blockDim.x) {
        float v = tsh[k];
        float dl = (k < TABN - 1) ? (tsh[k + 1] - v) : 0.f;
        g_tab[f][k] = make_float2(v, dl);
    }
}

// ---------------- K3: fused conv -> RBF -> conv^T -> residual ----------------
// One block per 64x64 output tile. 256 blocks = 16 batches x 16 tiles.
__global__ void __launch_bounds__(256, 2)
main_kernel(const float* __restrict__ input, const float* __restrict__ net_input) {
    __shared__ __align__(16) float xs[76 * XS];   // x halo tile, rows L=-6..69, col idx = c+6
    __shared__ __align__(16) float as_[70 * AS];  // a tile, idx = (r+3, c+3), r,c in [-3,67)
    __shared__ float red[8];

    int blk  = blockIdx.x;
    int b    = blk >> 4;
    int tile = blk & 15;
    int ty0  = (tile >> 2) << 6;
    int tx0  = (tile & 3) << 6;
    int tid  = threadIdx.x;

    const float* ibase = input + b * IMG * IMG;

    // load x halo (76 rows x 78 cols) with symmetric reflection
    for (int idx = tid; idx < 76 * 78; idx += 256) {
        int ri = idx / 78, ci = idx - ri * 78;
        int gy = ty0 + ri - 6;
        int gx = tx0 + ci - 6;
        gy = (gy < 0) ? (-1 - gy) : ((gy >= IMG) ? (2 * IMG - 1 - gy) : gy);
        gx = (gx < 0) ? (-1 - gx) : ((gx >= IMG) ? (2 * IMG - 1 - gx) : gx);
        xs[ri * XS + ci] = ibase[gy * IMG + gx];
    }

    // phase-A mapping: 252 threads each compute a 5-row x 4-col patch of the a-region
    bool actA = tid < 252;
    int rg = tid / 18, cg = tid - rg * 18;   // rg<14, cg<18
    int r0 = -3 + 5 * rg;                    // a rows r0..r0+4 (tile-local)
    int c0 = -3 + 4 * cg;                    // a cols c0..c0+3 (cg=17 has 2 junk cols)

    // phase-B mapping: 4x4 output block per thread
    int tyq = tid >> 4, txq = tid & 15;
    int ob = tyq << 2, oc = txq << 2;

    float oacc[16];
    #pragma unroll
    for (int i = 0; i < 16; i++) oacc[i] = 0.f;

    __syncthreads();

    #pragma unroll 1
    for (int f = 0; f < NF; f++) {
        // weights -> registers (uniform-address LDG, L1-hot)
        float wreg[KK];
        const float4* wp = (const float4*)(g_w + f * 52);
        #pragma unroll
        for (int v = 0; v < 12; v++) {
            float4 w4 = __ldg(wp + v);
            wreg[4 * v] = w4.x; wreg[4 * v + 1] = w4.y;
            wreg[4 * v + 2] = w4.z; wreg[4 * v + 3] = w4.w;
        }
        wreg[48] = __ldg(g_w + f * 52 + 48);

        float acc[20];
        if (actA) {
            #pragma unroll
            for (int i = 0; i < 20; i++) acc[i] = 0.f;
            // z = w corr x : sliding 11-row window, each row used by up to 5 outputs
            #pragma unroll
            for (int wr = 0; wr < 11; wr++) {
                const float* xp = xs + (r0 + 3 + wr) * XS + 4 * cg;  // x col base = c0-3 -> idx 4cg (16B aligned)
                float4 v0 = *(const float4*)xp;
                float4 v1 = *(const float4*)(xp + 4);
                float2 v2 = *(const float2*)(xp + 8);
                float xr[10] = {v0.x, v0.y, v0.z, v0.w, v1.x, v1.y, v1.z, v1.w, v2.x, v2.y};
                #pragma unroll
                for (int i = 0; i < 5; i++) {
                    int p = wr - i;                  // forward conv: x row = r-3+p
                    if (p >= 0 && p < 7) {
                        #pragma unroll
                        for (int q = 0; q < 7; q++) {
                            float wv = wreg[p * 7 + q];
                            #pragma unroll
                            for (int j = 0; j < 4; j++)
                                acc[i * 4 + j] += wv * xr[q + j];
                        }
                    }
                }
            }
            // RBF via table lerp; zero outside the image (conv^T zero-pads a)
            const float2* tb = g_tab[f];
            #pragma unroll
            for (int i = 0; i < 5; i++) {
                int gr = ty0 + r0 + i;
                bool rok = (gr >= 0) && (gr < IMG);
                #pragma unroll
                for (int j = 0; j < 4; j++) {
                    float t = (acc[i * 4 + j] + 16.f) * 64.f;
                    t = fminf(fmaxf(t, 0.f), 2047.99f);
                    int ix = (int)t;
                    float fr = t - (float)ix;
                    float2 tv = __ldg(tb + ix);
                    float a = tv.x + fr * tv.y;
                    int gc = tx0 + c0 + j;
                    if (!rok || gc < 0 || gc >= IMG) a = 0.f;
                    acc[i * 4 + j] = a;
                }
            }
        }
        __syncthreads();   // previous phase-B reads of as_ complete
        if (actA) {
            #pragma unroll
            for (int i = 0; i < 5; i++) {
                float4 st = make_float4(acc[i * 4], acc[i * 4 + 1], acc[i * 4 + 2], acc[i * 4 + 3]);
                *(float4*)(as_ + (r0 + i + 3) * AS + (c0 + 3)) = st;  // col idx 4cg: aligned
            }
        }
        __syncthreads();   // a tile ready

        // conv^T gather: convt[y,x] += sum_{p,q} w[p,q] * a[y+3-p, x+3-q]
        #pragma unroll
        for (int wrb = 0; wrb < 10; wrb++) {
            const float* ap = as_ + (ob + wrb) * AS + oc;  // a row L = ob-3+wrb, col base = oc-3 -> idx oc
            float4 u0 = *(const float4*)ap;
            float4 u1 = *(const float4*)(ap + 4);
            float2 u2 = *(const float2*)(ap + 8);
            float ar[10] = {u0.x, u0.y, u0.z, u0.w, u1.x, u1.y, u1.z, u1.w, u2.x, u2.y};
            #pragma unroll
            for (int i = 0; i < 4; i++) {
                int p = i + 6 - wrb;
                if (p >= 0 && p < 7) {
                    #pragma unroll
                    for (int q = 0; q < 7; q++) {
                        float wv = wreg[p * 7 + q];
                        #pragma unroll
                        for (int j = 0; j < 4; j++)
                            oacc[i * 4 + j] += wv * ar[j + 6 - q];
                    }
                }
            }
        }
    }

    // epilogue: r = input - convt - net_input ; per-block sum(r^2)
    const float* nbase = net_input + b * IMG * IMG;
    float* rbase = g_r + b * IMG * IMG;
    float ss = 0.f;
    #pragma unroll
    for (int i = 0; i < 4; i++) {
        int gy = ty0 + ob + i;
        int go = gy * IMG + tx0 + oc;
        float4 iv = *(const float4*)(ibase + go);
        float4 nv = *(const float4*)(nbase + go);
        float4 rv;
        rv.x = iv.x - oacc[i * 4 + 0] - nv.x;
        rv.y = iv.y - oacc[i * 4 + 1] - nv.y;
        rv.z = iv.z - oacc[i * 4 + 2] - nv.z;
        rv.w = iv.w - oacc[i * 4 + 3] - nv.w;
        *(float4*)(rbase + go) = rv;
        ss += rv.x * rv.x + rv.y * rv.y + rv.z * rv.z + rv.w * rv.w;
    }
    // deterministic block reduction
    #pragma unroll
    for (int o = 16; o > 0; o >>= 1) ss += __shfl_down_sync(0xffffffffu, ss, o);
    if ((tid & 31) == 0) red[tid >> 5] = ss;
    __syncthreads();
    if (tid == 0) {
        float s = 0.f;
        #pragma unroll
        for (int w = 0; w < 8; w++) s += red[w];
        g_partial[blk] = s;
    }
}

// ---------------- K4a: per-batch prox scale ----------------
__global__ void scale_kernel(const float* __restrict__ stdn, const float* __restrict__ alpha) {
    int b = blockIdx.x;
    if (threadIdx.x == 0) {
        float s = 0.f;
        #pragma unroll
        for (int t = 0; t < 16; t++) s += g_partial[b * 16 + t];
        float nr = sqrtf(s);
        float k = expf(alpha[0]) * stdn[b] * 256.f;   // sqrt(1*256*256) = 256
        g_scale[b] = fminf(1.f, k / (nr + 1e-12f));
    }
}

// ---------------- K4b: out = net_input + r * scale[b] ----------------
__global__ void final_kernel(const float* __restrict__ net_input, float* __restrict__ out) {
    int v = blockIdx.x * blockDim.x + threadIdx.x;  // float4 index
    if (v >= NB * IMG * IMG / 4) return;
    int b = v >> 14;  // 65536/4 float4 per batch
    float sc = g_scale[b];
    float4 rr = ((const float4*)g_r)[v];
    float4 nn = ((const float4*)net_input)[v];
    float4 o;
    o.x = nn.x + rr.x * sc;
    o.y = nn.y + rr.y * sc;
    o.z = nn.z + rr.z * sc;
    o.w = nn.w + rr.w * sc;
    ((float4*)out)[v] = o;
}

extern "C" void kernel_launch(void* const* d_in, const int* in_sizes, int n_in,
                              void* d_out, int out_size) {
    const float* input     = (const float*)d_in[0];
    const float* stdn      = (const float*)d_in[1];
    // d_in[2] = rbf_data (unused)
    const float* net_input = (const float*)d_in[3];
    const float* cw        = (const float*)d_in[4];
    const float* sf        = (const float*)d_in[5];
    const float* alpha     = (const float*)d_in[6];
    const float* rbw       = (const float*)d_in[7];
    const float* rbc       = (const float*)d_in[8];
    float* out = (float*)d_out;

    prep_kernel<<<1, 64>>>(cw, sf);
    table_kernel<<<NF, 256>>>(rbw, rbc);
    main_kernel<<<256, 256>>>(input, net_input);
    scale_kernel<<<NB, 32>>>(stdn, alpha);
    final_kernel<<<1024, 256>>>(net_input, out);
}